// round 2
// baseline (speedup 1.0000x reference)
#include <cuda_runtime.h>

#define D_MODEL 2048
#define BB 2
#define SS 2048
#define HH 16
#define DHD 128
#define PAST 2048
#define TOTAL 4096
#define BHH 32
#define M_ROWS 4096
#define QK_SCALE 0.08838834764831845f

// Scratch (allocation-free rule: __device__ globals)
__device__ float g_Q[BHH * (size_t)SS * DHD];        // (bh, s, dh), pre-scaled by 1/sqrt(dh)
__device__ float g_attn[BB * (size_t)SS * D_MODEL];  // (b, s, d_model)

// ---------------------------------------------------------------------------
// Copy past K/V into the first PAST rows of each bh's cache slot in d_out
// ---------------------------------------------------------------------------
__global__ void copy_past_kernel(const float4* __restrict__ pk,
                                 const float4* __restrict__ pv,
                                 float4* __restrict__ kc,
                                 float4* __restrict__ vc) {
    int i = blockIdx.x * blockDim.x + threadIdx.x;
    if (i >= BHH * PAST * DHD / 4) return;
    int bh  = i >> 16;            // / (PAST*DHD/4 = 65536)
    int rem = i & 65535;
    int dst = (bh << 17) + rem;   // bh * (TOTAL*DHD/4 = 131072)
    kc[dst] = pk[i];
    vc[dst] = pv[i];
}

// ---------------------------------------------------------------------------
// SGEMM: C[m][n] = sum_k A[m][k] * W[n][k]   (both row-major, K contiguous)
// 128x128 tile, BK=8, 256 threads, 8x8 per-thread, register prefetch.
// MODE 0: -> g_Q (head-split layout, scaled)   MODE 1/2: -> K/V cache rows
// MODE 3: -> plain row-major out
// ---------------------------------------------------------------------------
#define GBM 128
#define GBN 128
#define GBK 8
#define GLD 132   // padded leading dim: conflict-free transpose stores

template <int MODE>
__global__ __launch_bounds__(256) void sgemm_kernel(
    const float* __restrict__ A, const float* __restrict__ W,
    float* __restrict__ C) {
    __shared__ float As[GBK * GLD];
    __shared__ float Bs[GBK * GLD];

    int t  = threadIdx.x;
    int m0 = blockIdx.y * GBM;
    int n0 = blockIdx.x * GBN;
    int tx = t & 15, ty = t >> 4;
    int lrow = t >> 1;
    int kq   = (t & 1) * 4;

    const float* Ap = A + (size_t)(m0 + lrow) * D_MODEL + kq;
    const float* Bp = W + (size_t)(n0 + lrow) * D_MODEL + kq;

    float acc[8][8];
#pragma unroll
    for (int i = 0; i < 8; i++)
#pragma unroll
        for (int j = 0; j < 8; j++) acc[i][j] = 0.0f;

    float4 av = *(const float4*)Ap;
    float4 bv = *(const float4*)Bp;

    const int NT = D_MODEL / GBK;  // 256
    for (int kt = 0; kt < NT; kt++) {
        __syncthreads();
        As[(kq + 0) * GLD + lrow] = av.x;
        As[(kq + 1) * GLD + lrow] = av.y;
        As[(kq + 2) * GLD + lrow] = av.z;
        As[(kq + 3) * GLD + lrow] = av.w;
        Bs[(kq + 0) * GLD + lrow] = bv.x;
        Bs[(kq + 1) * GLD + lrow] = bv.y;
        Bs[(kq + 2) * GLD + lrow] = bv.z;
        Bs[(kq + 3) * GLD + lrow] = bv.w;
        __syncthreads();
        if (kt + 1 < NT) {
            av = *(const float4*)(Ap + (size_t)(kt + 1) * GBK);
            bv = *(const float4*)(Bp + (size_t)(kt + 1) * GBK);
        }
#pragma unroll
        for (int k = 0; k < GBK; k++) {
            float4 a0 = *(const float4*)&As[k * GLD + ty * 4];
            float4 a1 = *(const float4*)&As[k * GLD + 64 + ty * 4];
            float4 b0 = *(const float4*)&Bs[k * GLD + tx * 4];
            float4 b1 = *(const float4*)&Bs[k * GLD + 64 + tx * 4];
            float ar[8] = {a0.x, a0.y, a0.z, a0.w, a1.x, a1.y, a1.z, a1.w};
            float br[8] = {b0.x, b0.y, b0.z, b0.w, b1.x, b1.y, b1.z, b1.w};
#pragma unroll
            for (int i = 0; i < 8; i++)
#pragma unroll
                for (int j = 0; j < 8; j++) acc[i][j] += ar[i] * br[j];
        }
    }

#pragma unroll
    for (int i = 0; i < 8; i++) {
        int mr = (i < 4) ? (ty * 4 + i) : (64 + ty * 4 + (i - 4));
        int m  = m0 + mr;
#pragma unroll
        for (int jj = 0; jj < 2; jj++) {
            int n = n0 + jj * 64 + tx * 4;
            float4 v;
            v.x = acc[i][jj * 4 + 0];
            v.y = acc[i][jj * 4 + 1];
            v.z = acc[i][jj * 4 + 2];
            v.w = acc[i][jj * 4 + 3];
            if (MODE == 0) { v.x *= QK_SCALE; v.y *= QK_SCALE; v.z *= QK_SCALE; v.w *= QK_SCALE; }
            size_t idx;
            if (MODE == 3) {
                idx = (size_t)m * D_MODEL + n;
            } else {
                int bb = m >> 11, ss = m & 2047;
                int hd = n >> 7,  di = n & 127;
                if (MODE == 0)
                    idx = ((size_t)(bb * HH + hd) * SS + ss) * DHD + di;
                else
                    idx = ((size_t)(bb * HH + hd) * TOTAL + (PAST + ss)) * DHD + di;
            }
            *(float4*)&C[idx] = v;
        }
    }
}

// ---------------------------------------------------------------------------
// Flash attention (fp32, causal with KV cache prefix).
// Block = (bh, 64-query tile). BN=64 keys/iter, dh=128. 256 threads (16x16).
// smem: Qs[64][128] natural, Ks transposed [128][64] XOR-swizzled (float4
// chunks), Vs[64][128] natural, Ps[64][64] natural. 112 KB -> 2 CTA/SM.
// ---------------------------------------------------------------------------
#define FBM 64
#define FBN 64
#define FA_SMEM ((64 * 128 + 128 * 64 + 64 * 128 + 64 * 64) * 4)  // 114688 B

__global__ __launch_bounds__(256, 2) void flash_attn_kernel(
    const float* __restrict__ Q, const float* __restrict__ Kc,
    const float* __restrict__ Vc, float* __restrict__ Out) {
    extern __shared__ float sm[];
    float* Qs = sm;                    // [64][128]
    float* Ks = Qs + 64 * 128;         // [128][64] swizzled
    float* Vs = Ks + 128 * 64;         // [64][128]
    float* Ps = Vs + 64 * 128;         // [64][64]

    int t    = threadIdx.x;
    int tx   = t & 15, ty = t >> 4;
    int warp = t >> 5, lane = t & 31;
    int rl = lane >> 2;                // 0..7
    int dq = lane & 3;                 // 0..3
    int r_ld = warp * 8 + rl;          // load row 0..63

    int bh = blockIdx.y;
    int q0 = (gridDim.x - 1 - blockIdx.x) * FBM;  // big tiles launch first

    const float* Qb = Q  + (size_t)bh * SS * DHD;
    const float* Kb = Kc + (size_t)bh * TOTAL * DHD;
    const float* Vb = Vc + (size_t)bh * TOTAL * DHD;

    // Load Q tile (natural layout), coalesced
#pragma unroll
    for (int db = 0; db < 32; db += 4) {
        int dc = db + dq;
        *(float4*)&Qs[r_ld * DHD + dc * 4] =
            *(const float4*)&Qb[(size_t)(q0 + r_ld) * DHD + dc * 4];
    }

    float m_i[4], l_i[4], o[4][8];
#pragma unroll
    for (int r = 0; r < 4; r++) {
        m_i[r] = -1e30f;
        l_i[r] = 0.0f;
#pragma unroll
        for (int c = 0; c < 8; c++) o[r][c] = 0.0f;
    }

    int nfull = (PAST + q0) >> 6;
    for (int kt = 0; kt <= nfull; kt++) {
        int k0 = kt << 6;
        bool masked = (kt == nfull);
        __syncthreads();  // prior reads of Ks/Vs/Ps done (and Q stores on kt=0)

        // Load K (transposed + swizzled) and V (natural)
#pragma unroll
        for (int db = 0; db < 32; db += 4) {
            int dc = db + dq;
            float4 kv = *(const float4*)&Kb[(size_t)(k0 + r_ld) * DHD + dc * 4];
            float kvv[4] = {kv.x, kv.y, kv.z, kv.w};
#pragma unroll
            for (int c = 0; c < 4; c++) {
                int d = dc * 4 + c;
                int chunk = (r_ld >> 2) ^ (d & 15);
                Ks[d * 64 + chunk * 4 + (r_ld & 3)] = kvv[c];
            }
            *(float4*)&Vs[r_ld * DHD + dc * 4] =
                *(const float4*)&Vb[(size_t)(k0 + r_ld) * DHD + dc * 4];
        }
        __syncthreads();

        // S = Q K^T  (rows ty*4+r, cols tx*4+c)
        float s[4][4];
#pragma unroll
        for (int r = 0; r < 4; r++)
#pragma unroll
            for (int c = 0; c < 4; c++) s[r][c] = 0.0f;
#pragma unroll 8
        for (int d = 0; d < 128; d++) {
            float4 b4 = *(const float4*)&Ks[d * 64 + ((tx ^ (d & 15)) << 2)];
            float a0 = Qs[(ty * 4 + 0) * DHD + d];
            float a1 = Qs[(ty * 4 + 1) * DHD + d];
            float a2 = Qs[(ty * 4 + 2) * DHD + d];
            float a3 = Qs[(ty * 4 + 3) * DHD + d];
            s[0][0] += a0 * b4.x; s[0][1] += a0 * b4.y; s[0][2] += a0 * b4.z; s[0][3] += a0 * b4.w;
            s[1][0] += a1 * b4.x; s[1][1] += a1 * b4.y; s[1][2] += a1 * b4.z; s[1][3] += a1 * b4.w;
            s[2][0] += a2 * b4.x; s[2][1] += a2 * b4.y; s[2][2] += a2 * b4.z; s[2][3] += a2 * b4.w;
            s[3][0] += a3 * b4.x; s[3][1] += a3 * b4.y; s[3][2] += a3 * b4.z; s[3][3] += a3 * b4.w;
        }

        if (masked) {
#pragma unroll
            for (int r = 0; r < 4; r++)
#pragma unroll
                for (int c = 0; c < 4; c++)
                    if (tx * 4 + c > ty * 4 + r) s[r][c] = -1e30f;
        }

        // Online softmax (row reductions across the 16 tx lanes of each ty)
#pragma unroll
        for (int r = 0; r < 4; r++) {
            float rm = fmaxf(fmaxf(s[r][0], s[r][1]), fmaxf(s[r][2], s[r][3]));
#pragma unroll
            for (int off = 8; off; off >>= 1)
                rm = fmaxf(rm, __shfl_xor_sync(0xffffffffu, rm, off));
            float mn = fmaxf(m_i[r], rm);
            float sc = __expf(m_i[r] - mn);
            float rs = 0.0f;
#pragma unroll
            for (int c = 0; c < 4; c++) {
                float p = __expf(s[r][c] - mn);
                s[r][c] = p;
                rs += p;
            }
#pragma unroll
            for (int off = 8; off; off >>= 1)
                rs += __shfl_xor_sync(0xffffffffu, rs, off);
            l_i[r] = l_i[r] * sc + rs;
            m_i[r] = mn;
#pragma unroll
            for (int c = 0; c < 8; c++) o[r][c] *= sc;
        }

        // Stage P
#pragma unroll
        for (int r = 0; r < 4; r++) {
            float4 pv4;
            pv4.x = s[r][0]; pv4.y = s[r][1]; pv4.z = s[r][2]; pv4.w = s[r][3];
            *(float4*)&Ps[(ty * 4 + r) * 64 + tx * 4] = pv4;
        }
        __syncthreads();

        // O += P V
#pragma unroll 4
        for (int j = 0; j < 64; j++) {
            float a0 = Ps[(ty * 4 + 0) * 64 + j];
            float a1 = Ps[(ty * 4 + 1) * 64 + j];
            float a2 = Ps[(ty * 4 + 2) * 64 + j];
            float a3 = Ps[(ty * 4 + 3) * 64 + j];
            float4 v0 = *(const float4*)&Vs[j * DHD + tx * 4];
            float4 v1 = *(const float4*)&Vs[j * DHD + 64 + tx * 4];
            o[0][0] += a0 * v0.x; o[0][1] += a0 * v0.y; o[0][2] += a0 * v0.z; o[0][3] += a0 * v0.w;
            o[0][4] += a0 * v1.x; o[0][5] += a0 * v1.y; o[0][6] += a0 * v1.z; o[0][7] += a0 * v1.w;
            o[1][0] += a1 * v0.x; o[1][1] += a1 * v0.y; o[1][2] += a1 * v0.z; o[1][3] += a1 * v0.w;
            o[1][4] += a1 * v1.x; o[1][5] += a1 * v1.y; o[1][6] += a1 * v1.z; o[1][7] += a1 * v1.w;
            o[2][0] += a2 * v0.x; o[2][1] += a2 * v0.y; o[2][2] += a2 * v0.z; o[2][3] += a2 * v0.w;
            o[2][4] += a2 * v1.x; o[2][5] += a2 * v1.y; o[2][6] += a2 * v1.z; o[2][7] += a2 * v1.w;
            o[3][0] += a3 * v0.x; o[3][1] += a3 * v0.y; o[3][2] += a3 * v0.z; o[3][3] += a3 * v0.w;
            o[3][4] += a3 * v1.x; o[3][5] += a3 * v1.y; o[3][6] += a3 * v1.z; o[3][7] += a3 * v1.w;
        }
    }

    // Epilogue: normalize and write to g_attn in (b, s, d_model) layout
    int b  = bh >> 4;
    int hd = bh & 15;
#pragma unroll
    for (int r = 0; r < 4; r++) {
        float inv = 1.0f / l_i[r];
        int srow = q0 + ty * 4 + r;
        float* dst = Out + ((size_t)(b * SS + srow) * D_MODEL) + hd * DHD;
        float4 w0, w1;
        w0.x = o[r][0] * inv; w0.y = o[r][1] * inv; w0.z = o[r][2] * inv; w0.w = o[r][3] * inv;
        w1.x = o[r][4] * inv; w1.y = o[r][5] * inv; w1.z = o[r][6] * inv; w1.w = o[r][7] * inv;
        *(float4*)&dst[tx * 4]      = w0;
        *(float4*)&dst[64 + tx * 4] = w1;
    }
}

// ---------------------------------------------------------------------------
extern "C" void kernel_launch(void* const* d_in, const int* in_sizes, int n_in,
                              void* d_out, int out_size) {
    const float* x  = (const float*)d_in[0];
    const float* pk = (const float*)d_in[1];
    const float* pv = (const float*)d_in[2];
    const float* Wq = (const float*)d_in[3];
    const float* Wk = (const float*)d_in[4];
    const float* Wv = (const float*)d_in[5];
    const float* Wo = (const float*)d_in[6];

    float* out = (float*)d_out;
    float* kc  = out + (size_t)BB * SS * D_MODEL;           // K cache (bh, 4096, 128)
    float* vc  = kc + (size_t)BHH * TOTAL * DHD;            // V cache

    float *gQ = nullptr, *gA = nullptr;
    cudaGetSymbolAddress((void**)&gQ, g_Q);
    cudaGetSymbolAddress((void**)&gA, g_attn);

    cudaFuncSetAttribute(flash_attn_kernel,
                         cudaFuncAttributeMaxDynamicSharedMemorySize, FA_SMEM);

    // 1) copy past KV into cache outputs
    copy_past_kernel<<<(BHH * PAST * DHD / 4 + 255) / 256, 256>>>(
        (const float4*)pk, (const float4*)pv, (float4*)kc, (float4*)vc);

    // 2) Q/K/V projections
    dim3 ggrid(D_MODEL / GBN, M_ROWS / GBM);  // (16, 32)
    sgemm_kernel<0><<<ggrid, 256>>>(x, Wq, gQ);
    sgemm_kernel<1><<<ggrid, 256>>>(x, Wk, kc);
    sgemm_kernel<2><<<ggrid, 256>>>(x, Wv, vc);

    // 3) causal attention
    flash_attn_kernel<<<dim3(SS / FBM, BHH), 256, FA_SMEM>>>(gQ, kc, vc, gA);

    // 4) output projection
    sgemm_kernel<3><<<ggrid, 256>>>(gA, Wo, out);
}

// round 4
// speedup vs baseline: 2.2827x; 2.2827x over previous
#include <cuda_runtime.h>
#include <cstdint>

#define D_MODEL 2048
#define BB 2
#define SS 2048
#define HH 16
#define DHD 128
#define PAST 2048
#define TOTAL 4096
#define BHH 32
#define M_ROWS 4096
#define QK_SCALE 0.08838834764831845f

// Scratch (allocation-free rule: __device__ globals)
__device__ float g_Q[BHH * (size_t)SS * DHD];        // (bh, s, dh), pre-scaled by 1/sqrt(dh)
__device__ float g_attn[BB * (size_t)SS * D_MODEL];  // (b, s, d_model)

// ---------------------------------------------------------------------------
// Helpers
// ---------------------------------------------------------------------------
__device__ __forceinline__ uint32_t to_tf32(float f) {
    uint32_t u;
    asm("cvt.rna.tf32.f32 %0, %1;" : "=r"(u) : "f"(f));
    return u;
}

__device__ __forceinline__ uint4 cvt4(float4 v) {
    uint4 r;
    r.x = to_tf32(v.x); r.y = to_tf32(v.y);
    r.z = to_tf32(v.z); r.w = to_tf32(v.w);
    return r;
}

__device__ __forceinline__ void mma_tf32(float* c,
                                         uint32_t a0, uint32_t a1, uint32_t a2, uint32_t a3,
                                         uint32_t b0, uint32_t b1) {
    asm volatile(
        "mma.sync.aligned.m16n8k8.row.col.f32.tf32.tf32.f32 "
        "{%0,%1,%2,%3}, {%4,%5,%6,%7}, {%8,%9}, {%0,%1,%2,%3};"
        : "+f"(c[0]), "+f"(c[1]), "+f"(c[2]), "+f"(c[3])
        : "r"(a0), "r"(a1), "r"(a2), "r"(a3), "r"(b0), "r"(b1));
}

// Fast exp on the FMA pipe (arg <= 0 always). rel err ~2e-6.
__device__ __forceinline__ float fexp(float x) {
    float t = fmaxf(x * 1.4426950408889634f, -126.0f);
    float r = t + 12582912.0f;              // 1.5 * 2^23 round-to-int trick
    float fn = r - 12582912.0f;             // = round(t)
    float f = t - fn;                       // f in [-0.5, 0.5]
    int n = __float_as_int(r) - 0x4B400000; // integer part
    float p = 0.0013333558f;
    p = fmaf(p, f, 0.0096181291f);
    p = fmaf(p, f, 0.055504109f);
    p = fmaf(p, f, 0.24022651f);
    p = fmaf(p, f, 0.69314718f);
    p = fmaf(p, f, 1.0f);
    return p * __int_as_float((n + 127) << 23);
}

// ---------------------------------------------------------------------------
// Copy past K/V into the first PAST rows of each bh's cache slot in d_out
// ---------------------------------------------------------------------------
__global__ void copy_past_kernel(const float4* __restrict__ pk,
                                 const float4* __restrict__ pv,
                                 float4* __restrict__ kc,
                                 float4* __restrict__ vc) {
    int i = blockIdx.x * blockDim.x + threadIdx.x;
    if (i >= BHH * PAST * DHD / 4) return;
    int bh  = i >> 16;
    int rem = i & 65535;
    int dst = (bh << 17) + rem;
    kc[dst] = pk[i];
    vc[dst] = pv[i];
}

// ---------------------------------------------------------------------------
// TF32 tensor-core GEMM: C[m][n] = sum_k A[m][k] * W[n][k]
// CTA 128x128, BK=32, 256 threads, 8 warps (2m x 4n), warp tile 64x32.
// smem rows padded to 48 words (== 16 mod 32 -> conflict-free LDS.128 frags).
// k-permutation: one float4 (4 consecutive k) feeds two m16n8k8 mmas.
// ---------------------------------------------------------------------------
#define GLDW 48
#define GEMM_SMEM (2 * 128 * GLDW * 4)

template <int MODE>
__global__ __launch_bounds__(256) void gemm_tf32_kernel(
    const float* __restrict__ A, const float* __restrict__ W,
    float* __restrict__ C) {
    extern __shared__ uint32_t smg[];
    uint32_t* As = smg;               // [128][48]
    uint32_t* Bs = smg + 128 * GLDW;  // [128][48]

    int t    = threadIdx.x;
    int warp = t >> 5, lane = t & 31;
    int gid  = lane >> 2, tid4 = lane & 3;
    int wm   = (warp & 1) * 64;
    int wn   = (warp >> 1) * 32;
    int m0   = blockIdx.y * 128;
    int n0   = blockIdx.x * 128;

    int srow = t >> 3;       // 0..31
    int sc4  = t & 7;        // 0..7 (float4 col)

    const float* Ap = A + (size_t)(m0 + srow) * D_MODEL + sc4 * 4;
    const float* Bp = W + (size_t)(n0 + srow) * D_MODEL + sc4 * 4;

    int soff[4];
#pragma unroll
    for (int i = 0; i < 4; i++) soff[i] = (srow + 32 * i) * GLDW + sc4 * 4;

    float acc[4][4][4];
#pragma unroll
    for (int mf = 0; mf < 4; mf++)
#pragma unroll
        for (int nf = 0; nf < 4; nf++)
#pragma unroll
            for (int c = 0; c < 4; c++) acc[mf][nf][c] = 0.0f;

    float4 pa[4], pb[4];
#pragma unroll
    for (int i = 0; i < 4; i++) {
        pa[i] = *(const float4*)(Ap + (size_t)(i * 32) * D_MODEL);
        pb[i] = *(const float4*)(Bp + (size_t)(i * 32) * D_MODEL);
    }

    const int NT = D_MODEL / 32;  // 64
    for (int kt = 0; kt < NT; kt++) {
        __syncthreads();
#pragma unroll
        for (int i = 0; i < 4; i++) {
            *(uint4*)&As[soff[i]] = cvt4(pa[i]);
            *(uint4*)&Bs[soff[i]] = cvt4(pb[i]);
        }
        __syncthreads();
        if (kt + 1 < NT) {
            const float* ap = Ap + (kt + 1) * 32;
            const float* bp = Bp + (kt + 1) * 32;
#pragma unroll
            for (int i = 0; i < 4; i++) {
                pa[i] = *(const float4*)(ap + (size_t)(i * 32) * D_MODEL);
                pb[i] = *(const float4*)(bp + (size_t)(i * 32) * D_MODEL);
            }
        }
#pragma unroll
        for (int jj = 0; jj < 2; jj++) {
            uint4 bq[4];
#pragma unroll
            for (int nf = 0; nf < 4; nf++)
                bq[nf] = *(const uint4*)&Bs[(wn + 8 * nf + gid) * GLDW + jj * 16 + tid4 * 4];
#pragma unroll
            for (int mf = 0; mf < 4; mf++) {
                uint4 al = *(const uint4*)&As[(wm + 16 * mf + gid) * GLDW + jj * 16 + tid4 * 4];
                uint4 ah = *(const uint4*)&As[(wm + 16 * mf + gid + 8) * GLDW + jj * 16 + tid4 * 4];
#pragma unroll
                for (int nf = 0; nf < 4; nf++) {
                    mma_tf32(acc[mf][nf], al.x, ah.x, al.y, ah.y, bq[nf].x, bq[nf].y);
                    mma_tf32(acc[mf][nf], al.z, ah.z, al.w, ah.w, bq[nf].z, bq[nf].w);
                }
            }
        }
    }

    // Epilogue
#pragma unroll
    for (int mf = 0; mf < 4; mf++)
#pragma unroll
        for (int nf = 0; nf < 4; nf++)
#pragma unroll
            for (int h = 0; h < 2; h++) {
                int m = m0 + wm + 16 * mf + gid + 8 * h;
                int n = n0 + wn + 8 * nf + 2 * tid4;
                float2 v;
                v.x = acc[mf][nf][2 * h];
                v.y = acc[mf][nf][2 * h + 1];
                if (MODE == 0) { v.x *= QK_SCALE; v.y *= QK_SCALE; }
                size_t idx;
                if (MODE == 3) {
                    idx = (size_t)m * D_MODEL + n;
                } else {
                    int bb = m >> 11, ss = m & 2047;
                    int hd = n >> 7,  di = n & 127;
                    if (MODE == 0)
                        idx = ((size_t)(bb * HH + hd) * SS + ss) * DHD + di;
                    else
                        idx = ((size_t)(bb * HH + hd) * TOTAL + (PAST + ss)) * DHD + di;
                }
                *(float2*)&C[idx] = v;
            }
}

// ---------------------------------------------------------------------------
// Flash attention with tf32 tensor cores.
// CTA: 64 q-rows x 64 keys/iter, 256 threads, 8 warps.
// Warp w: S rows (w&3)*16, key-half (w>>2)*32; O rows same, d-half (w>>2)*64.
// smem pads: Qs/Ks 132 (4g+t banks), Vs 136 (8t+g banks), Ps 68.
// ---------------------------------------------------------------------------
#define QLD 132
#define VLD 136
#define PLD 68
#define FA_SMEM ((64 * QLD + 64 * QLD + 64 * VLD + 64 * PLD) * 4 + 1024)

__global__ __launch_bounds__(256) void flash_attn_tc_kernel(
    const float* __restrict__ Q, const float* __restrict__ Kc,
    const float* __restrict__ Vc, float* __restrict__ Out) {
    extern __shared__ uint32_t sm[];
    uint32_t* Qs = sm;                   // [64][132] tf32
    uint32_t* Ks = Qs + 64 * QLD;        // [64][132] tf32
    uint32_t* Vs = Ks + 64 * QLD;        // [64][136] tf32
    uint32_t* Ps = Vs + 64 * VLD;        // [64][68]  tf32
    float* pmax  = (float*)(Ps + 64 * PLD);  // [64][2]
    float* psum  = pmax + 128;               // [64][2]

    int t    = threadIdx.x;
    int warp = t >> 5, lane = t & 31;
    int gid  = lane >> 2, tid4 = lane & 3;
    int half = warp >> 2;       // 0/1
    int mq   = (warp & 3) * 16; // warp's row base

    int bh = blockIdx.y;
    int q0 = (gridDim.x - 1 - blockIdx.x) * 64;

    const float* Qb = Q  + (size_t)bh * SS * DHD;
    const float* Kb = Kc + (size_t)bh * TOTAL * DHD;
    const float* Vb = Vc + (size_t)bh * TOTAL * DHD;

    // Stage Q once (convert to tf32): row=(t>>5)+8i, c4=t&31
    {
        int row = t >> 5, c4 = t & 31;
#pragma unroll
        for (int i = 0; i < 8; i++) {
            int r = row + 8 * i;
            float4 v = *(const float4*)&Qb[(size_t)(q0 + r) * DHD + c4 * 4];
            *(uint4*)&Qs[r * QLD + c4 * 4] = cvt4(v);
        }
    }

    float m0r = -1e30f, m1r = -1e30f, l0 = 0.0f, l1 = 0.0f;
    float po[8][4];
#pragma unroll
    for (int nf = 0; nf < 8; nf++)
#pragma unroll
        for (int c = 0; c < 4; c++) po[nf][c] = 0.0f;

    int nkt = (PAST + q0) / 64 + 1;
    for (int kt = 0; kt < nkt; kt++) {
        int k0 = kt * 64;
        bool masked = (kt == nkt - 1);

        __syncthreads();  // prior P/V reads done; (kt=0: Q staging done)
        {
            int row = t >> 5, c4 = t & 31;
#pragma unroll
            for (int i = 0; i < 8; i++) {
                int r = row + 8 * i;
                float4 kv = *(const float4*)&Kb[(size_t)(k0 + r) * DHD + c4 * 4];
                float4 vv = *(const float4*)&Vb[(size_t)(k0 + r) * DHD + c4 * 4];
                *(uint4*)&Ks[r * QLD + c4 * 4] = cvt4(kv);
                *(uint4*)&Vs[r * VLD + c4 * 4] = cvt4(vv);
            }
        }
        __syncthreads();

        // S = Q K^T : warp computes 16x32
        float sc[4][4];
#pragma unroll
        for (int nf = 0; nf < 4; nf++)
#pragma unroll
            for (int c = 0; c < 4; c++) sc[nf][c] = 0.0f;

#pragma unroll 4
        for (int kk = 0; kk < 16; kk++) {
            uint32_t a0 = Qs[(mq + gid) * QLD + kk * 8 + tid4];
            uint32_t a1 = Qs[(mq + gid + 8) * QLD + kk * 8 + tid4];
            uint32_t a2 = Qs[(mq + gid) * QLD + kk * 8 + tid4 + 4];
            uint32_t a3 = Qs[(mq + gid + 8) * QLD + kk * 8 + tid4 + 4];
#pragma unroll
            for (int nf = 0; nf < 4; nf++) {
                int brow = half * 32 + nf * 8 + gid;
                uint32_t b0 = Ks[brow * QLD + kk * 8 + tid4];
                uint32_t b1 = Ks[brow * QLD + kk * 8 + tid4 + 4];
                mma_tf32(sc[nf], a0, a1, a2, a3, b0, b1);
            }
        }

        if (masked) {
#pragma unroll
            for (int nf = 0; nf < 4; nf++)
#pragma unroll
                for (int c = 0; c < 4; c++) {
                    int col = half * 32 + nf * 8 + 2 * tid4 + (c & 1);
                    int row = mq + gid + 8 * (c >> 1);
                    if (col > row) sc[nf][c] = -1e30f;
                }
        }

        // Row-max partials (quad shuffle over tid4 lanes)
        float rm0 = -1e30f, rm1 = -1e30f;
#pragma unroll
        for (int nf = 0; nf < 4; nf++) {
            rm0 = fmaxf(rm0, fmaxf(sc[nf][0], sc[nf][1]));
            rm1 = fmaxf(rm1, fmaxf(sc[nf][2], sc[nf][3]));
        }
#pragma unroll
        for (int off = 1; off <= 2; off <<= 1) {
            rm0 = fmaxf(rm0, __shfl_xor_sync(0xffffffffu, rm0, off));
            rm1 = fmaxf(rm1, __shfl_xor_sync(0xffffffffu, rm1, off));
        }
        if (tid4 == 0) {
            pmax[(mq + gid) * 2 + half]     = rm0;
            pmax[(mq + gid + 8) * 2 + half] = rm1;
        }
        __syncthreads();

        float mt0 = fmaxf(pmax[(mq + gid) * 2], pmax[(mq + gid) * 2 + 1]);
        float mt1 = fmaxf(pmax[(mq + gid + 8) * 2], pmax[(mq + gid + 8) * 2 + 1]);
        float mn0 = fmaxf(m0r, mt0);
        float mn1 = fmaxf(m1r, mt1);
        float alpha0 = fexp(m0r - mn0);
        float alpha1 = fexp(m1r - mn1);
        m0r = mn0; m1r = mn1;

        float rs0 = 0.0f, rs1 = 0.0f;
#pragma unroll
        for (int nf = 0; nf < 4; nf++) {
            float p0 = fexp(sc[nf][0] - mn0);
            float p1 = fexp(sc[nf][1] - mn0);
            float p2 = fexp(sc[nf][2] - mn1);
            float p3 = fexp(sc[nf][3] - mn1);
            rs0 += p0 + p1;
            rs1 += p2 + p3;
            int colb = half * 32 + nf * 8 + 2 * tid4;
            uint2 u01; u01.x = to_tf32(p0); u01.y = to_tf32(p1);
            uint2 u23; u23.x = to_tf32(p2); u23.y = to_tf32(p3);
            *(uint2*)&Ps[(mq + gid) * PLD + colb]     = u01;
            *(uint2*)&Ps[(mq + gid + 8) * PLD + colb] = u23;
        }
#pragma unroll
        for (int off = 1; off <= 2; off <<= 1) {
            rs0 += __shfl_xor_sync(0xffffffffu, rs0, off);
            rs1 += __shfl_xor_sync(0xffffffffu, rs1, off);
        }
        if (tid4 == 0) {
            psum[(mq + gid) * 2 + half]     = rs0;
            psum[(mq + gid + 8) * 2 + half] = rs1;
        }

        // Rescale O accumulators
#pragma unroll
        for (int nf = 0; nf < 8; nf++) {
            po[nf][0] *= alpha0; po[nf][1] *= alpha0;
            po[nf][2] *= alpha1; po[nf][3] *= alpha1;
        }
        __syncthreads();

        l0 = l0 * alpha0 + psum[(mq + gid) * 2] + psum[(mq + gid) * 2 + 1];
        l1 = l1 * alpha1 + psum[(mq + gid + 8) * 2] + psum[(mq + gid + 8) * 2 + 1];

        // O += P V : warp computes rows mq..mq+15, cols half*64..+63
#pragma unroll 4
        for (int kk = 0; kk < 8; kk++) {
            uint32_t a0 = Ps[(mq + gid) * PLD + kk * 8 + tid4];
            uint32_t a1 = Ps[(mq + gid + 8) * PLD + kk * 8 + tid4];
            uint32_t a2 = Ps[(mq + gid) * PLD + kk * 8 + tid4 + 4];
            uint32_t a3 = Ps[(mq + gid + 8) * PLD + kk * 8 + tid4 + 4];
#pragma unroll
            for (int nf = 0; nf < 8; nf++) {
                int col = half * 64 + nf * 8 + gid;
                uint32_t b0 = Vs[(kk * 8 + tid4) * VLD + col];
                uint32_t b1 = Vs[(kk * 8 + tid4 + 4) * VLD + col];
                mma_tf32(po[nf], a0, a1, a2, a3, b0, b1);
            }
        }
    }

    // Epilogue: normalize, write (b, s, d_model)
    float inv0 = 1.0f / l0;
    float inv1 = 1.0f / l1;
    int b  = bh >> 4;
    int hd = bh & 15;
    int row0 = q0 + mq + gid;
    int row1 = row0 + 8;
#pragma unroll
    for (int nf = 0; nf < 8; nf++) {
        int col = hd * DHD + half * 64 + nf * 8 + 2 * tid4;
        float2 v0, v1;
        v0.x = po[nf][0] * inv0; v0.y = po[nf][1] * inv0;
        v1.x = po[nf][2] * inv1; v1.y = po[nf][3] * inv1;
        *(float2*)&Out[(size_t)(b * SS + row0) * D_MODEL + col] = v0;
        *(float2*)&Out[(size_t)(b * SS + row1) * D_MODEL + col] = v1;
    }
}

// ---------------------------------------------------------------------------
extern "C" void kernel_launch(void* const* d_in, const int* in_sizes, int n_in,
                              void* d_out, int out_size) {
    const float* x  = (const float*)d_in[0];
    const float* pk = (const float*)d_in[1];
    const float* pv = (const float*)d_in[2];
    const float* Wq = (const float*)d_in[3];
    const float* Wk = (const float*)d_in[4];
    const float* Wv = (const float*)d_in[5];
    const float* Wo = (const float*)d_in[6];

    float* out = (float*)d_out;
    float* kc  = out + (size_t)BB * SS * D_MODEL;
    float* vc  = kc + (size_t)BHH * TOTAL * DHD;

    float *gQ = nullptr, *gA = nullptr;
    cudaGetSymbolAddress((void**)&gQ, g_Q);
    cudaGetSymbolAddress((void**)&gA, g_attn);

    cudaFuncSetAttribute(gemm_tf32_kernel<0>, cudaFuncAttributeMaxDynamicSharedMemorySize, GEMM_SMEM);
    cudaFuncSetAttribute(gemm_tf32_kernel<1>, cudaFuncAttributeMaxDynamicSharedMemorySize, GEMM_SMEM);
    cudaFuncSetAttribute(gemm_tf32_kernel<2>, cudaFuncAttributeMaxDynamicSharedMemorySize, GEMM_SMEM);
    cudaFuncSetAttribute(gemm_tf32_kernel<3>, cudaFuncAttributeMaxDynamicSharedMemorySize, GEMM_SMEM);
    cudaFuncSetAttribute(flash_attn_tc_kernel, cudaFuncAttributeMaxDynamicSharedMemorySize, FA_SMEM);

    // 1) copy past KV into cache outputs
    copy_past_kernel<<<(BHH * PAST * DHD / 4 + 255) / 256, 256>>>(
        (const float4*)pk, (const float4*)pv, (float4*)kc, (float4*)vc);

    // 2) Q/K/V projections (tf32 tensor cores)
    dim3 ggrid(D_MODEL / 128, M_ROWS / 128);  // (16, 32)
    gemm_tf32_kernel<0><<<ggrid, 256, GEMM_SMEM>>>(x, Wq, gQ);
    gemm_tf32_kernel<1><<<ggrid, 256, GEMM_SMEM>>>(x, Wk, kc);
    gemm_tf32_kernel<2><<<ggrid, 256, GEMM_SMEM>>>(x, Wv, vc);

    // 3) causal attention (tf32 tensor cores)
    flash_attn_tc_kernel<<<dim3(SS / 64, BHH), 256, FA_SMEM>>>(gQ, kc, vc, gA);

    // 4) output projection
    gemm_tf32_kernel<3><<<ggrid, 256, GEMM_SMEM>>>(gA, Wo, out);
}

// round 5
// speedup vs baseline: 2.6342x; 1.1540x over previous
#include <cuda_runtime.h>
#include <cstdint>

#define D_MODEL 2048
#define BB 2
#define SS 2048
#define HH 16
#define DHD 128
#define PAST 2048
#define TOTAL 4096
#define BHH 32
#define M_ROWS 4096
#define QK_SCALE 0.08838834764831845f

// Scratch (allocation-free rule: __device__ globals)
__device__ float g_Q[BHH * (size_t)SS * DHD];        // (bh, s, dh), pre-scaled
__device__ float g_attn[BB * (size_t)SS * D_MODEL];  // (b, s, d_model)

// ---------------------------------------------------------------------------
// Helpers
// ---------------------------------------------------------------------------
__device__ __forceinline__ uint32_t to_tf32(float f) {
    uint32_t u;
    asm("cvt.rna.tf32.f32 %0, %1;" : "=r"(u) : "f"(f));
    return u;
}

__device__ __forceinline__ uint4 cvt4(float4 v) {
    uint4 r;
    r.x = to_tf32(v.x); r.y = to_tf32(v.y);
    r.z = to_tf32(v.z); r.w = to_tf32(v.w);
    return r;
}

__device__ __forceinline__ void mma_tf32(float* c,
                                         uint32_t a0, uint32_t a1, uint32_t a2, uint32_t a3,
                                         uint32_t b0, uint32_t b1) {
    asm volatile(
        "mma.sync.aligned.m16n8k8.row.col.f32.tf32.tf32.f32 "
        "{%0,%1,%2,%3}, {%4,%5,%6,%7}, {%8,%9}, {%0,%1,%2,%3};"
        : "+f"(c[0]), "+f"(c[1]), "+f"(c[2]), "+f"(c[3])
        : "r"(a0), "r"(a1), "r"(a2), "r"(a3), "r"(b0), "r"(b1));
}

// Fast exp on the FMA pipe (arg <= 0 always). rel err ~2e-6.
__device__ __forceinline__ float fexp(float x) {
    float t = fmaxf(x * 1.4426950408889634f, -126.0f);
    float r = t + 12582912.0f;
    float fn = r - 12582912.0f;
    float f = t - fn;
    int n = __float_as_int(r) - 0x4B400000;
    float p = 0.0013333558f;
    p = fmaf(p, f, 0.0096181291f);
    p = fmaf(p, f, 0.055504109f);
    p = fmaf(p, f, 0.24022651f);
    p = fmaf(p, f, 0.69314718f);
    p = fmaf(p, f, 1.0f);
    return p * __int_as_float((n + 127) << 23);
}

__device__ __forceinline__ void cpasync16(void* smem_dst, const void* gsrc) {
    uint32_t s = (uint32_t)__cvta_generic_to_shared(smem_dst);
    asm volatile("cp.async.cg.shared.global [%0], [%1], 16;" :: "r"(s), "l"(gsrc));
}
__device__ __forceinline__ void cpasync_commit() {
    asm volatile("cp.async.commit_group;");
}
__device__ __forceinline__ void cpasync_wait1() {
    asm volatile("cp.async.wait_group 1;");
}

// ---------------------------------------------------------------------------
// Copy past K/V into the first PAST rows of each bh's cache slot in d_out
// ---------------------------------------------------------------------------
__global__ void copy_past_kernel(const float4* __restrict__ pk,
                                 const float4* __restrict__ pv,
                                 float4* __restrict__ kc,
                                 float4* __restrict__ vc) {
    int i = blockIdx.x * blockDim.x + threadIdx.x;
    if (i >= BHH * PAST * DHD / 4) return;
    int bh  = i >> 16;
    int rem = i & 65535;
    int dst = (bh << 17) + rem;
    kc[dst] = pk[i];
    vc[dst] = pv[i];
}

// ---------------------------------------------------------------------------
// TF32 tensor-core GEMM with 3-stage cp.async pipeline.
// C[m][n] = sum_k A[m][k] * W[n][k], CTA 128x128, BK=32, 256 thr, 8 warps.
// smem: 3 stages of raw f32 (A 128x48-padded + B 128x48), cvt on consumer.
// FUSED=1: gridDim.z selects Wq/Wk/Wv + Q/KV-cache epilogues.
// FUSED=0: plain row-major C (output projection).
// ---------------------------------------------------------------------------
#define GLDW 48
#define GSTAGE (2 * 128 * GLDW)              // floats per stage
#define GEMM_SMEM (3 * GSTAGE * 4)           // 147456 B

template <int FUSED>
__global__ __launch_bounds__(256) void gemm_pipe_kernel(
    const float* __restrict__ A,
    const float* __restrict__ W0, const float* __restrict__ W1,
    const float* __restrict__ W2,
    float* __restrict__ C0, float* __restrict__ C1, float* __restrict__ C2) {
    extern __shared__ float smf[];

    int t    = threadIdx.x;
    int warp = t >> 5, lane = t & 31;
    int gid  = lane >> 2, tid4 = lane & 3;
    int wm   = (warp & 1) * 64;
    int wn   = (warp >> 1) * 32;
    int m0   = blockIdx.y * 128;
    int n0   = blockIdx.x * 128;
    int z    = FUSED ? blockIdx.z : 0;

    const float* Wp = FUSED ? (z == 0 ? W0 : (z == 1 ? W1 : W2)) : W0;
    float*       C  = FUSED ? (z == 0 ? C0 : (z == 1 ? C1 : C2)) : C0;

    const float* Ab = A  + (size_t)m0 * D_MODEL;
    const float* Bb = Wp + (size_t)n0 * D_MODEL;

    float acc[4][4][4];
#pragma unroll
    for (int mf = 0; mf < 4; mf++)
#pragma unroll
        for (int nf = 0; nf < 4; nf++)
#pragma unroll
            for (int c = 0; c < 4; c++) acc[mf][nf][c] = 0.0f;

    const int NT = D_MODEL / 32;  // 64

    // async stage loader: 4 chunks A + 4 chunks B per thread
#define GEMM_ISSUE(KT, STG)                                                     \
    {                                                                           \
        float* As_ = smf + (STG) * GSTAGE;                                      \
        float* Bs_ = As_ + 128 * GLDW;                                          \
        const float* ab = Ab + (KT) * 32;                                       \
        const float* bb = Bb + (KT) * 32;                                       \
        _Pragma("unroll")                                                       \
        for (int j = 0; j < 4; j++) {                                           \
            int g  = t + 256 * j;                                               \
            int r  = g >> 3;                                                    \
            int c4 = g & 7;                                                     \
            cpasync16(As_ + r * GLDW + c4 * 4, ab + (size_t)r * D_MODEL + c4 * 4); \
            cpasync16(Bs_ + r * GLDW + c4 * 4, bb + (size_t)r * D_MODEL + c4 * 4); \
        }                                                                       \
    }

    GEMM_ISSUE(0, 0); cpasync_commit();
    GEMM_ISSUE(1, 1); cpasync_commit();

    for (int kt = 0; kt < NT; kt++) {
        cpasync_wait1();
        __syncthreads();
        if (kt + 2 < NT) GEMM_ISSUE(kt + 2, (kt + 2) % 3);
        cpasync_commit();

        const float* As = smf + (kt % 3) * GSTAGE;
        const float* Bs = As + 128 * GLDW;
#pragma unroll
        for (int jj = 0; jj < 2; jj++) {
            uint4 bq[4];
#pragma unroll
            for (int nf = 0; nf < 4; nf++)
                bq[nf] = cvt4(*(const float4*)&Bs[(wn + 8 * nf + gid) * GLDW + jj * 16 + tid4 * 4]);
#pragma unroll
            for (int mf = 0; mf < 4; mf++) {
                uint4 al = cvt4(*(const float4*)&As[(wm + 16 * mf + gid) * GLDW + jj * 16 + tid4 * 4]);
                uint4 ah = cvt4(*(const float4*)&As[(wm + 16 * mf + gid + 8) * GLDW + jj * 16 + tid4 * 4]);
#pragma unroll
                for (int nf = 0; nf < 4; nf++) {
                    mma_tf32(acc[mf][nf], al.x, ah.x, al.y, ah.y, bq[nf].x, bq[nf].y);
                    mma_tf32(acc[mf][nf], al.z, ah.z, al.w, ah.w, bq[nf].z, bq[nf].w);
                }
            }
        }
    }
#undef GEMM_ISSUE

    // Epilogue
#pragma unroll
    for (int mf = 0; mf < 4; mf++)
#pragma unroll
        for (int nf = 0; nf < 4; nf++)
#pragma unroll
            for (int h = 0; h < 2; h++) {
                int m = m0 + wm + 16 * mf + gid + 8 * h;
                int n = n0 + wn + 8 * nf + 2 * tid4;
                float2 v;
                v.x = acc[mf][nf][2 * h];
                v.y = acc[mf][nf][2 * h + 1];
                size_t idx;
                if (!FUSED) {
                    idx = (size_t)m * D_MODEL + n;
                } else {
                    int bb = m >> 11, ss = m & 2047;
                    int hd = n >> 7,  di = n & 127;
                    if (z == 0) {
                        v.x *= QK_SCALE; v.y *= QK_SCALE;
                        idx = ((size_t)(bb * HH + hd) * SS + ss) * DHD + di;
                    } else {
                        idx = ((size_t)(bb * HH + hd) * TOTAL + (PAST + ss)) * DHD + di;
                    }
                }
                *(float2*)&C[idx] = v;
            }
}

// ---------------------------------------------------------------------------
// Flash attention, tf32 tensor cores, warp-private rows.
// CTA: 128 q-rows x 64 keys/iter, 256 threads, 8 warps.
// Warp w owns q-rows [w*16, w*16+16), ALL keys, ALL 128 d-cols:
//   -> softmax reductions are quad-shuffles only; P is warp-private.
// smem: Qs[128][132], Ks[64][132], Vs[64][136], Ps[128][68]  (tf32) = 171 KB.
// ---------------------------------------------------------------------------
#define FBM 128
#define QLD 132
#define VLD 136
#define PLD 68
#define FA_SMEM ((FBM * QLD + 64 * QLD + 64 * VLD + FBM * PLD) * 4)

__global__ __launch_bounds__(256) void flash_attn_tc_kernel(
    const float* __restrict__ Q, const float* __restrict__ Kc,
    const float* __restrict__ Vc, float* __restrict__ Out) {
    extern __shared__ uint32_t sm[];
    uint32_t* Qs = sm;                    // [128][132]
    uint32_t* Ks = Qs + FBM * QLD;        // [64][132]
    uint32_t* Vs = Ks + 64 * QLD;         // [64][136]
    uint32_t* Ps = Vs + 64 * VLD;         // [128][68]

    int t    = threadIdx.x;
    int warp = t >> 5, lane = t & 31;
    int gid  = lane >> 2, tid4 = lane & 3;
    int mq   = warp * 16;

    int bh = blockIdx.y;
    int q0 = (gridDim.x - 1 - blockIdx.x) * FBM;  // big tiles launch first

    const float* Qb = Q  + (size_t)bh * SS * DHD;
    const float* Kb = Kc + (size_t)bh * TOTAL * DHD;
    const float* Vb = Vc + (size_t)bh * TOTAL * DHD;

    int lrow = t >> 5;       // 0..7
    int c4   = t & 31;       // 0..31 float4 col

    // Stage Q once (tf32)
#pragma unroll
    for (int i = 0; i < 16; i++) {
        int r = lrow + 8 * i;
        float4 v = *(const float4*)&Qb[(size_t)(q0 + r) * DHD + c4 * 4];
        *(uint4*)&Qs[r * QLD + c4 * 4] = cvt4(v);
    }

    float m0r = -1e30f, m1r = -1e30f, l0 = 0.0f, l1 = 0.0f;
    float po[16][4];
#pragma unroll
    for (int nf = 0; nf < 16; nf++)
#pragma unroll
        for (int c = 0; c < 4; c++) po[nf][c] = 0.0f;

    int nkt = (PAST + q0 + FBM) / 64;
    for (int kt = 0; kt < nkt; kt++) {
        int k0 = kt * 64;
        bool masked = (k0 >= PAST + q0);
        int rel = k0 - PAST - q0;

        // Issue K/V loads for this tile before the barrier (overlap prior tail)
        float4 kreg[8], vreg[8];
#pragma unroll
        for (int i = 0; i < 8; i++) {
            int r = lrow + 8 * i;
            kreg[i] = *(const float4*)&Kb[(size_t)(k0 + r) * DHD + c4 * 4];
            vreg[i] = *(const float4*)&Vb[(size_t)(k0 + r) * DHD + c4 * 4];
        }
        __syncthreads();  // prior PV reads of Ks/Vs done (kt=0: Q staging done)
#pragma unroll
        for (int i = 0; i < 8; i++) {
            int r = lrow + 8 * i;
            *(uint4*)&Ks[r * QLD + c4 * 4] = cvt4(kreg[i]);
            *(uint4*)&Vs[r * VLD + c4 * 4] = cvt4(vreg[i]);
        }
        __syncthreads();

        // S = Q K^T : warp computes 16 rows x 64 keys
        float sc[8][4];
#pragma unroll
        for (int nf = 0; nf < 8; nf++)
#pragma unroll
            for (int c = 0; c < 4; c++) sc[nf][c] = 0.0f;

#pragma unroll 4
        for (int kk = 0; kk < 16; kk++) {
            uint32_t a0 = Qs[(mq + gid) * QLD + kk * 8 + tid4];
            uint32_t a1 = Qs[(mq + gid + 8) * QLD + kk * 8 + tid4];
            uint32_t a2 = Qs[(mq + gid) * QLD + kk * 8 + tid4 + 4];
            uint32_t a3 = Qs[(mq + gid + 8) * QLD + kk * 8 + tid4 + 4];
#pragma unroll
            for (int nf = 0; nf < 8; nf++) {
                int brow = nf * 8 + gid;
                uint32_t b0 = Ks[brow * QLD + kk * 8 + tid4];
                uint32_t b1 = Ks[brow * QLD + kk * 8 + tid4 + 4];
                mma_tf32(sc[nf], a0, a1, a2, a3, b0, b1);
            }
        }

        if (masked) {
#pragma unroll
            for (int nf = 0; nf < 8; nf++)
#pragma unroll
                for (int c = 0; c < 4; c++) {
                    int col = nf * 8 + 2 * tid4 + (c & 1);
                    int row = mq + gid + 8 * (c >> 1);
                    if (col + rel > row) sc[nf][c] = -1e30f;
                }
        }

        // Warp-private online softmax (rows mq+gid, mq+gid+8)
        float rm0 = -1e30f, rm1 = -1e30f;
#pragma unroll
        for (int nf = 0; nf < 8; nf++) {
            rm0 = fmaxf(rm0, fmaxf(sc[nf][0], sc[nf][1]));
            rm1 = fmaxf(rm1, fmaxf(sc[nf][2], sc[nf][3]));
        }
#pragma unroll
        for (int off = 1; off <= 2; off <<= 1) {
            rm0 = fmaxf(rm0, __shfl_xor_sync(0xffffffffu, rm0, off));
            rm1 = fmaxf(rm1, __shfl_xor_sync(0xffffffffu, rm1, off));
        }
        float mn0 = fmaxf(m0r, rm0);
        float mn1 = fmaxf(m1r, rm1);
        float alpha0 = fexp(m0r - mn0);
        float alpha1 = fexp(m1r - mn1);
        m0r = mn0; m1r = mn1;

        float rs0 = 0.0f, rs1 = 0.0f;
#pragma unroll
        for (int nf = 0; nf < 8; nf++) {
            float p0 = fexp(sc[nf][0] - mn0);
            float p1 = fexp(sc[nf][1] - mn0);
            float p2 = fexp(sc[nf][2] - mn1);
            float p3 = fexp(sc[nf][3] - mn1);
            rs0 += p0 + p1;
            rs1 += p2 + p3;
            int colb = nf * 8 + 2 * tid4;
            uint2 u01; u01.x = to_tf32(p0); u01.y = to_tf32(p1);
            uint2 u23; u23.x = to_tf32(p2); u23.y = to_tf32(p3);
            *(uint2*)&Ps[(mq + gid) * PLD + colb]     = u01;
            *(uint2*)&Ps[(mq + gid + 8) * PLD + colb] = u23;
        }
#pragma unroll
        for (int off = 1; off <= 2; off <<= 1) {
            rs0 += __shfl_xor_sync(0xffffffffu, rs0, off);
            rs1 += __shfl_xor_sync(0xffffffffu, rs1, off);
        }
        l0 = l0 * alpha0 + rs0;
        l1 = l1 * alpha1 + rs1;

        // Rescale O accumulators
#pragma unroll
        for (int nf = 0; nf < 16; nf++) {
            po[nf][0] *= alpha0; po[nf][1] *= alpha0;
            po[nf][2] *= alpha1; po[nf][3] *= alpha1;
        }
        __syncwarp();  // P store -> P load, warp-private

        // O += P V : 16 rows x 128 d-cols
#pragma unroll 4
        for (int kk = 0; kk < 8; kk++) {
            uint32_t a0 = Ps[(mq + gid) * PLD + kk * 8 + tid4];
            uint32_t a1 = Ps[(mq + gid + 8) * PLD + kk * 8 + tid4];
            uint32_t a2 = Ps[(mq + gid) * PLD + kk * 8 + tid4 + 4];
            uint32_t a3 = Ps[(mq + gid + 8) * PLD + kk * 8 + tid4 + 4];
#pragma unroll
            for (int nf = 0; nf < 16; nf++) {
                int col = nf * 8 + gid;
                uint32_t b0 = Vs[(kk * 8 + tid4) * VLD + col];
                uint32_t b1 = Vs[(kk * 8 + tid4 + 4) * VLD + col];
                mma_tf32(po[nf], a0, a1, a2, a3, b0, b1);
            }
        }
    }

    // Epilogue: normalize, write (b, s, d_model)
    float inv0 = 1.0f / l0;
    float inv1 = 1.0f / l1;
    int b  = bh >> 4;
    int hd = bh & 15;
    int row0 = q0 + mq + gid;
    int row1 = row0 + 8;
#pragma unroll
    for (int nf = 0; nf < 16; nf++) {
        int col = hd * DHD + nf * 8 + 2 * tid4;
        float2 v0, v1;
        v0.x = po[nf][0] * inv0; v0.y = po[nf][1] * inv0;
        v1.x = po[nf][2] * inv1; v1.y = po[nf][3] * inv1;
        *(float2*)&Out[(size_t)(b * SS + row0) * D_MODEL + col] = v0;
        *(float2*)&Out[(size_t)(b * SS + row1) * D_MODEL + col] = v1;
    }
}

// ---------------------------------------------------------------------------
extern "C" void kernel_launch(void* const* d_in, const int* in_sizes, int n_in,
                              void* d_out, int out_size) {
    const float* x  = (const float*)d_in[0];
    const float* pk = (const float*)d_in[1];
    const float* pv = (const float*)d_in[2];
    const float* Wq = (const float*)d_in[3];
    const float* Wk = (const float*)d_in[4];
    const float* Wv = (const float*)d_in[5];
    const float* Wo = (const float*)d_in[6];

    float* out = (float*)d_out;
    float* kc  = out + (size_t)BB * SS * D_MODEL;
    float* vc  = kc + (size_t)BHH * TOTAL * DHD;

    float *gQ = nullptr, *gA = nullptr;
    cudaGetSymbolAddress((void**)&gQ, g_Q);
    cudaGetSymbolAddress((void**)&gA, g_attn);

    cudaFuncSetAttribute(gemm_pipe_kernel<1>, cudaFuncAttributeMaxDynamicSharedMemorySize, GEMM_SMEM);
    cudaFuncSetAttribute(gemm_pipe_kernel<0>, cudaFuncAttributeMaxDynamicSharedMemorySize, GEMM_SMEM);
    cudaFuncSetAttribute(flash_attn_tc_kernel, cudaFuncAttributeMaxDynamicSharedMemorySize, FA_SMEM);

    // 1) copy past KV into cache outputs
    copy_past_kernel<<<(BHH * PAST * DHD / 4 + 255) / 256, 256>>>(
        (const float4*)pk, (const float4*)pv, (float4*)kc, (float4*)vc);

    // 2) fused Q/K/V projections (tf32 tensor cores, cp.async pipeline)
    dim3 qkv_grid(D_MODEL / 128, M_ROWS / 128, 3);  // (16, 32, 3)
    gemm_pipe_kernel<1><<<qkv_grid, 256, GEMM_SMEM>>>(x, Wq, Wk, Wv, gQ, kc, vc);

    // 3) causal attention (tf32 tensor cores)
    flash_attn_tc_kernel<<<dim3(SS / FBM, BHH), 256, FA_SMEM>>>(gQ, kc, vc, gA);

    // 4) output projection
    dim3 o_grid(D_MODEL / 128, M_ROWS / 128, 1);
    gemm_pipe_kernel<0><<<o_grid, 256, GEMM_SMEM>>>(gA, Wo, nullptr, nullptr, out, nullptr, nullptr);
}

// round 6
// speedup vs baseline: 3.1286x; 1.1877x over previous
#include <cuda_runtime.h>
#include <cstdint>

#define D_MODEL 2048
#define BB 2
#define SS 2048
#define HH 16
#define DHD 128
#define PAST 2048
#define TOTAL 4096
#define BHH 32
#define M_ROWS 4096
#define QK_SCALE 0.08838834764831845f

// Scratch (allocation-free rule: __device__ globals). All hold tf32 bit patterns.
__device__ uint32_t g_Xt[(size_t)M_ROWS * D_MODEL];          // x, tf32
__device__ uint32_t g_Wt[4 * (size_t)D_MODEL * D_MODEL];     // Wq,Wk,Wv,Wo tf32
__device__ uint32_t g_Qt[(size_t)BHH * SS * DHD];            // Q (bh,s,dh) tf32, pre-scaled
__device__ uint32_t g_Kt[(size_t)BHH * TOTAL * DHD];         // K (bh,key,dh) tf32
__device__ uint32_t g_Vt[(size_t)BHH * DHD * TOTAL];         // V TRANSPOSED (bh,dh,key) tf32
__device__ uint32_t g_At[(size_t)BB * SS * D_MODEL];         // attn (b,s,dm) tf32

// ---------------------------------------------------------------------------
// Helpers
// ---------------------------------------------------------------------------
__device__ __forceinline__ uint32_t to_tf32(float f) {
    uint32_t u;
    asm("cvt.rna.tf32.f32 %0, %1;" : "=r"(u) : "f"(f));
    return u;
}

__device__ __forceinline__ uint4 cvt4(float4 v) {
    uint4 r;
    r.x = to_tf32(v.x); r.y = to_tf32(v.y);
    r.z = to_tf32(v.z); r.w = to_tf32(v.w);
    return r;
}

__device__ __forceinline__ void mma_tf32(float* c,
                                         uint32_t a0, uint32_t a1, uint32_t a2, uint32_t a3,
                                         uint32_t b0, uint32_t b1) {
    asm volatile(
        "mma.sync.aligned.m16n8k8.row.col.f32.tf32.tf32.f32 "
        "{%0,%1,%2,%3}, {%4,%5,%6,%7}, {%8,%9}, {%0,%1,%2,%3};"
        : "+f"(c[0]), "+f"(c[1]), "+f"(c[2]), "+f"(c[3])
        : "r"(a0), "r"(a1), "r"(a2), "r"(a3), "r"(b0), "r"(b1));
}

// Fast exp on the FMA pipe (arg <= 0 always). rel err ~2e-6.
__device__ __forceinline__ float fexp(float x) {
    float t = fmaxf(x * 1.4426950408889634f, -126.0f);
    float r = t + 12582912.0f;
    float fn = r - 12582912.0f;
    float f = t - fn;
    int n = __float_as_int(r) - 0x4B400000;
    float p = 0.0013333558f;
    p = fmaf(p, f, 0.0096181291f);
    p = fmaf(p, f, 0.055504109f);
    p = fmaf(p, f, 0.24022651f);
    p = fmaf(p, f, 0.69314718f);
    p = fmaf(p, f, 1.0f);
    return p * __int_as_float((n + 127) << 23);
}

__device__ __forceinline__ void cpasync16(void* smem_dst, const void* gsrc) {
    uint32_t s = (uint32_t)__cvta_generic_to_shared(smem_dst);
    asm volatile("cp.async.cg.shared.global [%0], [%1], 16;" :: "r"(s), "l"(gsrc));
}
__device__ __forceinline__ void cpasync_commit() {
    asm volatile("cp.async.commit_group;");
}
__device__ __forceinline__ void cpasync_wait1() {
    asm volatile("cp.async.wait_group 1;");
}

// ---------------------------------------------------------------------------
// Prep kernels: converts + past-KV handling
// ---------------------------------------------------------------------------
__global__ void cvt_x_kernel(const float4* __restrict__ x, uint4* __restrict__ out) {
    int i = blockIdx.x * blockDim.x + threadIdx.x;
    if (i < M_ROWS * D_MODEL / 4) out[i] = cvt4(x[i]);
}

__global__ void cvt_w_kernel(const float4* __restrict__ w0, const float4* __restrict__ w1,
                             const float4* __restrict__ w2, const float4* __restrict__ w3,
                             uint4* __restrict__ out) {
    int z = blockIdx.y;
    const float4* src = (z == 0) ? w0 : (z == 1) ? w1 : (z == 2) ? w2 : w3;
    int i = blockIdx.x * blockDim.x + threadIdx.x;
    const int n4 = D_MODEL * D_MODEL / 4;
    if (i < n4) out[(size_t)z * n4 + i] = cvt4(src[i]);
}

// past K: straight copy to fp32 cache + tf32 scratch (same layout)
__global__ void copy_past_k_kernel(const float4* __restrict__ pk,
                                   float4* __restrict__ kc, uint4* __restrict__ kt) {
    int i = blockIdx.x * blockDim.x + threadIdx.x;
    if (i >= BHH * PAST * DHD / 4) return;
    int bh  = i >> 16;
    int rem = i & 65535;
    int dst = (bh << 17) + rem;   // bh * (TOTAL*DHD/4)
    float4 v = pk[i];
    kc[dst] = v;
    kt[dst] = cvt4(v);
}

// past V: fp32 cache copy + TRANSPOSED tf32 scratch (smem-tiled transpose)
__global__ __launch_bounds__(256) void transpose_past_v_kernel(
    const float* __restrict__ pv, float* __restrict__ vc, uint32_t* __restrict__ vt) {
    __shared__ float ts[32][33];
    int bh = blockIdx.z;
    int k0 = blockIdx.x * 32;
    int d0 = blockIdx.y * 32;
    int tx = threadIdx.x & 31, ty = threadIdx.x >> 5;  // (32, 8)

    const float* src = pv + ((size_t)bh * PAST + k0) * DHD + d0;
    float* cdst      = vc + ((size_t)bh * TOTAL + k0) * DHD + d0;
#pragma unroll
    for (int j = 0; j < 4; j++) {
        int r = ty + 8 * j;
        float v = src[(size_t)r * DHD + tx];
        cdst[(size_t)r * DHD + tx] = v;
        ts[r][tx] = v;
    }
    __syncthreads();
    uint32_t* tdst = vt + (size_t)bh * DHD * TOTAL;
#pragma unroll
    for (int j = 0; j < 4; j++) {
        int d = d0 + ty + 8 * j;
        tdst[(size_t)d * TOTAL + k0 + tx] = to_tf32(ts[tx][ty + 8 * j]);
    }
}

// ---------------------------------------------------------------------------
// TF32 tensor-core GEMM, 3-stage cp.async pipeline, tf32-bit inputs (no cvt).
// C[m][n] = sum_k A[m][k] * W[n][k], CTA 128x128, BK=32, 256 thr, 8 warps.
// FUSED=1: gridDim.z selects Wq/Wk/Wv; epilogues write Q/K/V scratch + caches.
// FUSED=0: plain fp32 row-major C (output projection).
// ---------------------------------------------------------------------------
#define GLDW 48
#define GSTAGE (2 * 128 * GLDW)
#define GEMM_SMEM (3 * GSTAGE * 4)

template <int FUSED>
__global__ __launch_bounds__(256) void gemm_pipe_kernel(
    const uint32_t* __restrict__ A, const uint32_t* __restrict__ Wt,
    float* __restrict__ C0, float* __restrict__ C1, float* __restrict__ C2,
    uint32_t* __restrict__ Qt, uint32_t* __restrict__ Kt, uint32_t* __restrict__ Vt) {
    extern __shared__ uint32_t smg[];

    int t    = threadIdx.x;
    int warp = t >> 5, lane = t & 31;
    int gid  = lane >> 2, tid4 = lane & 3;
    int wm   = (warp & 1) * 64;
    int wn   = (warp >> 1) * 32;
    int m0   = blockIdx.y * 128;
    int n0   = blockIdx.x * 128;
    int z    = FUSED ? blockIdx.z : 0;

    const uint32_t* Ab = A + (size_t)m0 * D_MODEL;
    const uint32_t* Bb = Wt + (FUSED ? (size_t)z * D_MODEL * D_MODEL : 0) + (size_t)n0 * D_MODEL;

    float acc[4][4][4];
#pragma unroll
    for (int mf = 0; mf < 4; mf++)
#pragma unroll
        for (int nf = 0; nf < 4; nf++)
#pragma unroll
            for (int c = 0; c < 4; c++) acc[mf][nf][c] = 0.0f;

    const int NT = D_MODEL / 32;  // 64

#define GEMM_ISSUE(KT, STG)                                                        \
    {                                                                              \
        uint32_t* As_ = smg + (STG) * GSTAGE;                                      \
        uint32_t* Bs_ = As_ + 128 * GLDW;                                          \
        const uint32_t* ab = Ab + (KT) * 32;                                       \
        const uint32_t* bb = Bb + (KT) * 32;                                       \
        _Pragma("unroll")                                                          \
        for (int j = 0; j < 4; j++) {                                              \
            int g  = t + 256 * j;                                                  \
            int r  = g >> 3;                                                       \
            int c4 = g & 7;                                                        \
            cpasync16(As_ + r * GLDW + c4 * 4, ab + (size_t)r * D_MODEL + c4 * 4); \
            cpasync16(Bs_ + r * GLDW + c4 * 4, bb + (size_t)r * D_MODEL + c4 * 4); \
        }                                                                          \
    }

    GEMM_ISSUE(0, 0); cpasync_commit();
    GEMM_ISSUE(1, 1); cpasync_commit();

    for (int kt = 0; kt < NT; kt++) {
        cpasync_wait1();
        __syncthreads();
        if (kt + 2 < NT) GEMM_ISSUE(kt + 2, (kt + 2) % 3);
        cpasync_commit();

        const uint32_t* As = smg + (kt % 3) * GSTAGE;
        const uint32_t* Bs = As + 128 * GLDW;
#pragma unroll
        for (int jj = 0; jj < 2; jj++) {
            uint4 bq[4];
#pragma unroll
            for (int nf = 0; nf < 4; nf++)
                bq[nf] = *(const uint4*)&Bs[(wn + 8 * nf + gid) * GLDW + jj * 16 + tid4 * 4];
#pragma unroll
            for (int mf = 0; mf < 4; mf++) {
                uint4 al = *(const uint4*)&As[(wm + 16 * mf + gid) * GLDW + jj * 16 + tid4 * 4];
                uint4 ah = *(const uint4*)&As[(wm + 16 * mf + gid + 8) * GLDW + jj * 16 + tid4 * 4];
#pragma unroll
                for (int nf = 0; nf < 4; nf++) {
                    mma_tf32(acc[mf][nf], al.x, ah.x, al.y, ah.y, bq[nf].x, bq[nf].y);
                    mma_tf32(acc[mf][nf], al.z, ah.z, al.w, ah.w, bq[nf].z, bq[nf].w);
                }
            }
        }
    }
#undef GEMM_ISSUE

    // Epilogue
#pragma unroll
    for (int mf = 0; mf < 4; mf++)
#pragma unroll
        for (int nf = 0; nf < 4; nf++)
#pragma unroll
            for (int h = 0; h < 2; h++) {
                int m = m0 + wm + 16 * mf + gid + 8 * h;
                int n = n0 + wn + 8 * nf + 2 * tid4;
                float2 v;
                v.x = acc[mf][nf][2 * h];
                v.y = acc[mf][nf][2 * h + 1];
                if (!FUSED) {
                    *(float2*)&C0[(size_t)m * D_MODEL + n] = v;
                } else {
                    int bb = m >> 11, ss = m & 2047;
                    int hd = n >> 7,  di = n & 127;
                    int bhh = bb * HH + hd;
                    if (z == 0) {
                        v.x *= QK_SCALE; v.y *= QK_SCALE;
                        uint2 u; u.x = to_tf32(v.x); u.y = to_tf32(v.y);
                        *(uint2*)&Qt[((size_t)bhh * SS + ss) * DHD + di] = u;
                    } else if (z == 1) {
                        size_t idx = ((size_t)bhh * TOTAL + (PAST + ss)) * DHD + di;
                        *(float2*)&C1[idx] = v;
                        uint2 u; u.x = to_tf32(v.x); u.y = to_tf32(v.y);
                        *(uint2*)&Kt[idx] = u;
                    } else {
                        size_t idx = ((size_t)bhh * TOTAL + (PAST + ss)) * DHD + di;
                        *(float2*)&C2[idx] = v;
                        size_t key = PAST + ss;
                        Vt[(size_t)bhh * DHD * TOTAL + (size_t)di * TOTAL + key]       = to_tf32(v.x);
                        Vt[(size_t)bhh * DHD * TOTAL + (size_t)(di + 1) * TOTAL + key] = to_tf32(v.y);
                    }
                }
            }
}

// ---------------------------------------------------------------------------
// Flash attention, tf32 tensor cores. Q fragments in registers, K/Vt staged
// via 2-stage cp.async double buffer, warp-private softmax, P smem-private.
// CTA: 128 q-rows x 64 keys/iter, 256 threads, 8 warps (warp w: rows w*16..+15,
// all keys, all 128 d). smem: Ks[2][64][144] + Vts[2][128][80] + Ps[128][80].
// ---------------------------------------------------------------------------
#define FBM 128
#define KLD 144
#define VTLD 80
#define PLD 80
#define FA_SMEM ((2 * 64 * KLD + 2 * 128 * VTLD + 128 * PLD) * 4)  // 196608

__global__ __launch_bounds__(256) void flash_attn_tc_kernel(
    const uint32_t* __restrict__ Qt, const uint32_t* __restrict__ Ktg,
    const uint32_t* __restrict__ Vtg, uint32_t* __restrict__ Out) {
    extern __shared__ uint32_t sm[];
    uint32_t* Ks  = sm;                      // [2][64][KLD]
    uint32_t* Vts = sm + 2 * 64 * KLD;       // [2][128][VTLD]
    uint32_t* Ps  = Vts + 2 * 128 * VTLD;    // [128][PLD]

    int t    = threadIdx.x;
    int warp = t >> 5, lane = t & 31;
    int gid  = lane >> 2, tid4 = lane & 3;
    int mq   = warp * 16;

    int bh = blockIdx.y;
    int q0 = (gridDim.x - 1 - blockIdx.x) * FBM;  // big tiles launch first

    const uint32_t* Kb = Ktg + (size_t)bh * TOTAL * DHD;
    const uint32_t* Vb = Vtg + (size_t)bh * DHD * TOTAL;

    // Q fragments in registers: rows mq+gid, mq+gid+8; k = jj*16 + 4*tid4 .. +3
    uint4 q0r[8], q1r[8];
    {
        const uint32_t* Qrow0 = Qt + ((size_t)bh * SS + (q0 + mq + gid)) * DHD + 4 * tid4;
        const uint32_t* Qrow1 = Qrow0 + 8 * DHD;
#pragma unroll
        for (int jj = 0; jj < 8; jj++) {
            q0r[jj] = *(const uint4*)&Qrow0[jj * 16];
            q1r[jj] = *(const uint4*)&Qrow1[jj * 16];
        }
    }

    float m0r = -1e30f, m1r = -1e30f, l0 = 0.0f, l1 = 0.0f;
    float po[16][4];
#pragma unroll
    for (int nf = 0; nf < 16; nf++)
#pragma unroll
        for (int c = 0; c < 4; c++) po[nf][c] = 0.0f;

#define FA_ISSUE(KT, STG)                                                          \
    {                                                                              \
        int k0_ = (KT) * 64;                                                       \
        uint32_t* ksd = Ks + (STG) * 64 * KLD;                                     \
        uint32_t* vsd = Vts + (STG) * 128 * VTLD;                                  \
        _Pragma("unroll")                                                          \
        for (int i = 0; i < 8; i++) {                                              \
            int id = t + 256 * i;                                                  \
            int r = id >> 5, c = id & 31;                                          \
            cpasync16(ksd + r * KLD + c * 4, Kb + (size_t)(k0_ + r) * DHD + c * 4);\
        }                                                                          \
        _Pragma("unroll")                                                          \
        for (int i = 0; i < 8; i++) {                                              \
            int id = t + 256 * i;                                                  \
            int d = id >> 4, kg = id & 15;                                         \
            cpasync16(vsd + d * VTLD + kg * 4, Vb + (size_t)d * TOTAL + k0_ + kg * 4); \
        }                                                                          \
    }

    int nkt = (PAST + q0 + FBM) / 64;
    FA_ISSUE(0, 0); cpasync_commit();

    for (int kt = 0; kt < nkt; kt++) {
        int k0 = kt * 64;
        bool masked = (k0 >= PAST + q0);
        int rel = k0 - PAST - q0;

        __syncthreads();  // all warps done reading stage (kt+1)&1 from iter kt-1
        if (kt + 1 < nkt) FA_ISSUE(kt + 1, (kt + 1) & 1);
        cpasync_commit();
        cpasync_wait1();
        __syncthreads();

        const uint32_t* ksb = Ks + (kt & 1) * 64 * KLD;
        const uint32_t* vsb = Vts + (kt & 1) * 128 * VTLD;

        // S = Q K^T : 16 rows x 64 keys
        float sc[8][4];
#pragma unroll
        for (int nf = 0; nf < 8; nf++)
#pragma unroll
            for (int c = 0; c < 4; c++) sc[nf][c] = 0.0f;

#pragma unroll
        for (int jj = 0; jj < 8; jj++) {
#pragma unroll
            for (int nf = 0; nf < 8; nf++) {
                uint4 b = *(const uint4*)&ksb[(nf * 8 + gid) * KLD + jj * 16 + 4 * tid4];
                mma_tf32(sc[nf], q0r[jj].x, q1r[jj].x, q0r[jj].y, q1r[jj].y, b.x, b.y);
                mma_tf32(sc[nf], q0r[jj].z, q1r[jj].z, q0r[jj].w, q1r[jj].w, b.z, b.w);
            }
        }

        if (masked) {
#pragma unroll
            for (int nf = 0; nf < 8; nf++)
#pragma unroll
                for (int c = 0; c < 4; c++) {
                    int col = nf * 8 + 2 * tid4 + (c & 1);
                    int row = mq + gid + 8 * (c >> 1);
                    if (col + rel > row) sc[nf][c] = -1e30f;
                }
        }

        // Warp-private online softmax (rows mq+gid, mq+gid+8)
        float rm0 = -1e30f, rm1 = -1e30f;
#pragma unroll
        for (int nf = 0; nf < 8; nf++) {
            rm0 = fmaxf(rm0, fmaxf(sc[nf][0], sc[nf][1]));
            rm1 = fmaxf(rm1, fmaxf(sc[nf][2], sc[nf][3]));
        }
#pragma unroll
        for (int off = 1; off <= 2; off <<= 1) {
            rm0 = fmaxf(rm0, __shfl_xor_sync(0xffffffffu, rm0, off));
            rm1 = fmaxf(rm1, __shfl_xor_sync(0xffffffffu, rm1, off));
        }
        float mn0 = fmaxf(m0r, rm0);
        float mn1 = fmaxf(m1r, rm1);
        float alpha0 = fexp(m0r - mn0);
        float alpha1 = fexp(m1r - mn1);
        m0r = mn0; m1r = mn1;

        __syncwarp();  // prior PV reads of Ps complete before overwrite
        float rs0 = 0.0f, rs1 = 0.0f;
#pragma unroll
        for (int nf = 0; nf < 8; nf++) {
            float p0 = fexp(sc[nf][0] - mn0);
            float p1 = fexp(sc[nf][1] - mn0);
            float p2 = fexp(sc[nf][2] - mn1);
            float p3 = fexp(sc[nf][3] - mn1);
            rs0 += p0 + p1;
            rs1 += p2 + p3;
            int colb = nf * 8 + 2 * tid4;
            uint2 u01; u01.x = to_tf32(p0); u01.y = to_tf32(p1);
            uint2 u23; u23.x = to_tf32(p2); u23.y = to_tf32(p3);
            *(uint2*)&Ps[(mq + gid) * PLD + colb]     = u01;
            *(uint2*)&Ps[(mq + gid + 8) * PLD + colb] = u23;
        }
#pragma unroll
        for (int off = 1; off <= 2; off <<= 1) {
            rs0 += __shfl_xor_sync(0xffffffffu, rs0, off);
            rs1 += __shfl_xor_sync(0xffffffffu, rs1, off);
        }
        l0 = l0 * alpha0 + rs0;
        l1 = l1 * alpha1 + rs1;

#pragma unroll
        for (int nf = 0; nf < 16; nf++) {
            po[nf][0] *= alpha0; po[nf][1] *= alpha0;
            po[nf][2] *= alpha1; po[nf][3] *= alpha1;
        }
        __syncwarp();  // P stores visible to warp

        // O += P V : A = Ps fragments, B = Vt (d-major, key-vectorized)
#pragma unroll
        for (int jj = 0; jj < 4; jj++) {
            uint4 pa0 = *(const uint4*)&Ps[(mq + gid) * PLD + jj * 16 + 4 * tid4];
            uint4 pa1 = *(const uint4*)&Ps[(mq + gid + 8) * PLD + jj * 16 + 4 * tid4];
#pragma unroll
            for (int nf = 0; nf < 16; nf++) {
                uint4 b = *(const uint4*)&vsb[(nf * 8 + gid) * VTLD + jj * 16 + 4 * tid4];
                mma_tf32(po[nf], pa0.x, pa1.x, pa0.y, pa1.y, b.x, b.y);
                mma_tf32(po[nf], pa0.z, pa1.z, pa0.w, pa1.w, b.z, b.w);
            }
        }
    }
#undef FA_ISSUE

    // Epilogue: normalize, convert to tf32 bits, write (b, s, d_model)
    float inv0 = 1.0f / l0;
    float inv1 = 1.0f / l1;
    int b  = bh >> 4;
    int hd = bh & 15;
    int row0 = q0 + mq + gid;
    int row1 = row0 + 8;
#pragma unroll
    for (int nf = 0; nf < 16; nf++) {
        int col = hd * DHD + nf * 8 + 2 * tid4;
        uint2 u0, u1;
        u0.x = to_tf32(po[nf][0] * inv0); u0.y = to_tf32(po[nf][1] * inv0);
        u1.x = to_tf32(po[nf][2] * inv1); u1.y = to_tf32(po[nf][3] * inv1);
        *(uint2*)&Out[(size_t)(b * SS + row0) * D_MODEL + col] = u0;
        *(uint2*)&Out[(size_t)(b * SS + row1) * D_MODEL + col] = u1;
    }
}

// ---------------------------------------------------------------------------
extern "C" void kernel_launch(void* const* d_in, const int* in_sizes, int n_in,
                              void* d_out, int out_size) {
    const float* x  = (const float*)d_in[0];
    const float* pk = (const float*)d_in[1];
    const float* pv = (const float*)d_in[2];
    const float* Wq = (const float*)d_in[3];
    const float* Wk = (const float*)d_in[4];
    const float* Wv = (const float*)d_in[5];
    const float* Wo = (const float*)d_in[6];

    float* out = (float*)d_out;
    float* kc  = out + (size_t)BB * SS * D_MODEL;
    float* vc  = kc + (size_t)BHH * TOTAL * DHD;

    uint32_t *gXt, *gWt, *gQt, *gKt, *gVt, *gAt;
    cudaGetSymbolAddress((void**)&gXt, g_Xt);
    cudaGetSymbolAddress((void**)&gWt, g_Wt);
    cudaGetSymbolAddress((void**)&gQt, g_Qt);
    cudaGetSymbolAddress((void**)&gKt, g_Kt);
    cudaGetSymbolAddress((void**)&gVt, g_Vt);
    cudaGetSymbolAddress((void**)&gAt, g_At);

    cudaFuncSetAttribute(gemm_pipe_kernel<1>, cudaFuncAttributeMaxDynamicSharedMemorySize, GEMM_SMEM);
    cudaFuncSetAttribute(gemm_pipe_kernel<0>, cudaFuncAttributeMaxDynamicSharedMemorySize, GEMM_SMEM);
    cudaFuncSetAttribute(flash_attn_tc_kernel, cudaFuncAttributeMaxDynamicSharedMemorySize, FA_SMEM);

    // 1) prep: convert x/W to tf32; past K copy+cvt; past V copy+transpose
    cvt_x_kernel<<<(M_ROWS * D_MODEL / 4 + 255) / 256, 256>>>(
        (const float4*)x, (uint4*)gXt);
    cvt_w_kernel<<<dim3((D_MODEL * D_MODEL / 4 + 255) / 256, 4), 256>>>(
        (const float4*)Wq, (const float4*)Wk, (const float4*)Wv, (const float4*)Wo,
        (uint4*)gWt);
    copy_past_k_kernel<<<(BHH * PAST * DHD / 4 + 255) / 256, 256>>>(
        (const float4*)pk, (float4*)kc, (uint4*)gKt);
    transpose_past_v_kernel<<<dim3(PAST / 32, DHD / 32, BHH), 256>>>(
        pv, vc, gVt);

    // 2) fused Q/K/V projections
    dim3 qkv_grid(D_MODEL / 128, M_ROWS / 128, 3);
    gemm_pipe_kernel<1><<<qkv_grid, 256, GEMM_SMEM>>>(
        gXt, gWt, nullptr, kc, vc, gQt, gKt, gVt);

    // 3) causal attention
    flash_attn_tc_kernel<<<dim3(SS / FBM, BHH), 256, FA_SMEM>>>(gQt, gKt, gVt, gAt);

    // 4) output projection (Wo is slot 3 of gWt)
    dim3 o_grid(D_MODEL / 128, M_ROWS / 128, 1);
    gemm_pipe_kernel<0><<<o_grid, 256, GEMM_SMEM>>>(
        gAt, gWt + 3 * (size_t)D_MODEL * D_MODEL, out, nullptr, nullptr,
        nullptr, nullptr, nullptr);
}